// round 2
// baseline (speedup 1.0000x reference)
#include <cuda_runtime.h>
#include <math.h>
#include <stdint.h>

// Problem constants (fixed by the dataset)
constexpr int cN   = 20000;
constexpr int cE   = 320000;
constexpr int cIN  = 512;
constexpr int cHID = 128;
constexpr int cH   = 8;
constexpr int cC   = 64;
constexpr int cHH  = cH * cHID;   // 1024

// ---------------------------------------------------------------------------
// Scratch (static __device__ globals; no allocation allowed)
// ---------------------------------------------------------------------------
__device__ float g_bufA[(size_t)cN * cHH];   // 80 MB
__device__ float g_bufB[(size_t)cN * cHH];   // 80 MB
__device__ float g_a1[cN * cH];
__device__ float g_a2[cN * cH];
__device__ int   g_cnt[cN];
__device__ int   g_rowptr[cN + 1];
__device__ int   g_cursor[cN];
__device__ int   g_srcsorted[cE];

// ---------------------------------------------------------------------------
// CSR build: histogram -> scan -> scatter (edges grouped by dst)
// ---------------------------------------------------------------------------
__global__ void zero_int_kernel(int* p, int n) {
    int i = blockIdx.x * blockDim.x + threadIdx.x;
    if (i < n) p[i] = 0;
}

__global__ void hist_kernel(const int* __restrict__ dst, int* __restrict__ cnt, int e) {
    int i = blockIdx.x * blockDim.x + threadIdx.x;
    if (i < e) atomicAdd(&cnt[dst[i]], 1);
}

// single block, 1024 threads; n = cN
__global__ void scan_kernel(const int* __restrict__ cnt, int* __restrict__ rowptr,
                            int* __restrict__ cursor, int n) {
    __shared__ int sh[1024];
    int tid = threadIdx.x;
    const int CH = (n + 1023) / 1024;
    int st = tid * CH;
    int s = 0;
    for (int i = 0; i < CH; i++) {
        int idx = st + i;
        if (idx < n) s += cnt[idx];
    }
    sh[tid] = s;
    __syncthreads();
    // Hillis-Steele inclusive scan
    for (int d = 1; d < 1024; d <<= 1) {
        int v = (tid >= d) ? sh[tid - d] : 0;
        __syncthreads();
        sh[tid] += v;
        __syncthreads();
    }
    int run = sh[tid] - s;   // exclusive prefix for this thread's chunk
    for (int i = 0; i < CH; i++) {
        int idx = st + i;
        if (idx < n) {
            rowptr[idx] = run;
            cursor[idx] = run;
            run += cnt[idx];
        }
    }
    if (tid == 1023) rowptr[n] = sh[1023];
}

__global__ void scatter_kernel(const int* __restrict__ src, const int* __restrict__ dst,
                               int* __restrict__ cursor, int* __restrict__ out, int e) {
    int i = blockIdx.x * blockDim.x + threadIdx.x;
    if (i < e) {
        int d = dst[i];
        int pos = atomicAdd(&cursor[d], 1);
        out[pos] = src[i];
    }
}

// ---------------------------------------------------------------------------
// Register-blocked SGEMM with fused bias.  W layout is head-blocked:
// element (i, h*HIDo + jj) lives at W[h*K*HIDo + i*HIDo + jj].  We require
// BN == HIDo so each column-block is a fully contiguous K x BN panel.
// ---------------------------------------------------------------------------
template<int BM, int BN, int BK, int TM, int TN>
__global__ __launch_bounds__((BM / TM) * (BN / TN))
void gemm_bias_kernel(const float* __restrict__ A, const float* __restrict__ W,
                      const float* __restrict__ bias, float* __restrict__ C,
                      int M, int K, int ldc) {
    constexpr int THREADS = (BM / TM) * (BN / TN);
    constexpr int TX = BN / TN;
    __shared__ float As[BK * BM];
    __shared__ float Bs[BK * BN];

    const int tid  = threadIdx.x;
    const int row0 = blockIdx.x * BM;
    const int col0 = blockIdx.y * BN;
    const float* Bp = W + (size_t)col0 * K;   // contiguous K x BN panel

    const int tx = tid % TX;
    const int ty = tid / TX;

    float acc[TM][TN];
#pragma unroll
    for (int i = 0; i < TM; i++)
#pragma unroll
        for (int j = 0; j < TN; j++) acc[i][j] = 0.f;

    for (int k0 = 0; k0 < K; k0 += BK) {
        // Load A tile (BM x BK), stored transposed As[k][m]
#pragma unroll
        for (int off = tid * 4; off < BM * BK; off += THREADS * 4) {
            int row = off / BK;
            int kk  = off % BK;
            float4 v = make_float4(0.f, 0.f, 0.f, 0.f);
            if (row0 + row < M)
                v = *reinterpret_cast<const float4*>(A + (size_t)(row0 + row) * K + k0 + kk);
            As[(kk + 0) * BM + row] = v.x;
            As[(kk + 1) * BM + row] = v.y;
            As[(kk + 2) * BM + row] = v.z;
            As[(kk + 3) * BM + row] = v.w;
        }
        // Load B tile (BK x BN) — contiguous
#pragma unroll
        for (int off = tid * 4; off < BK * BN; off += THREADS * 4) {
            *reinterpret_cast<float4*>(&Bs[off]) =
                *reinterpret_cast<const float4*>(Bp + (size_t)k0 * BN + off);
        }
        __syncthreads();

#pragma unroll
        for (int k = 0; k < BK; k++) {
            float a[TM], b[TN];
#pragma unroll
            for (int i = 0; i < TM; i++) a[i] = As[k * BM + ty * TM + i];
#pragma unroll
            for (int j = 0; j < TN; j++) b[j] = Bs[k * BN + tx * TN + j];
#pragma unroll
            for (int i = 0; i < TM; i++)
#pragma unroll
                for (int j = 0; j < TN; j++) acc[i][j] = fmaf(a[i], b[j], acc[i][j]);
        }
        __syncthreads();
    }

#pragma unroll
    for (int i = 0; i < TM; i++) {
        int r = row0 + ty * TM + i;
        if (r < M) {
#pragma unroll
            for (int j = 0; j < TN; j++) {
                int c = col0 + tx * TN + j;
                C[(size_t)r * ldc + c] = acc[i][j] + bias[c];
            }
        }
    }
}

// ---------------------------------------------------------------------------
// Per-node attention logits: a1[n,h] = ft[n, h*HIDo:] . al[h] + alb[h]
// one warp per (node, head)
// ---------------------------------------------------------------------------
__global__ void logits_kernel(const float* __restrict__ ft,
                              const float* __restrict__ al, const float* __restrict__ alb,
                              const float* __restrict__ ar, const float* __restrict__ arb,
                              float* __restrict__ a1, float* __restrict__ a2,
                              int Nn, int Hn, int HIDo, int ld) {
    int gw   = (blockIdx.x * blockDim.x + threadIdx.x) >> 5;
    int lane = threadIdx.x & 31;
    if (gw >= Nn * Hn) return;
    int n = gw / Hn;
    int h = gw - n * Hn;
    const float* fp = ft + (size_t)n * ld + h * HIDo;
    float s1 = 0.f, s2 = 0.f;
    for (int j = lane; j < HIDo; j += 32) {
        float f = fp[j];
        s1 = fmaf(f, al[h * HIDo + j], s1);
        s2 = fmaf(f, ar[h * HIDo + j], s2);
    }
    for (int o = 16; o; o >>= 1) {
        s1 += __shfl_xor_sync(0xffffffffu, s1, o);
        s2 += __shfl_xor_sync(0xffffffffu, s2, o);
    }
    if (lane == 0) {
        a1[n * Hn + h] = s1 + alb[h];
        a2[n * Hn + h] = s2 + arb[h];
    }
}

// ---------------------------------------------------------------------------
// Edge-softmax + aggregation + ELU.  One warp per (node, head).
// NR = HIDo/32 output registers per lane.
// ---------------------------------------------------------------------------
template<int NR>
__global__ void aggregate_kernel(const float* __restrict__ ft,
                                 const float* __restrict__ a1,
                                 const float* __restrict__ a2,
                                 const int* __restrict__ rowptr,
                                 const int* __restrict__ srcs,
                                 float* __restrict__ out,
                                 int Nn, int Hn, int ld) {
    constexpr int HIDo = NR * 32;
    int gw   = (blockIdx.x * blockDim.x + threadIdx.x) >> 5;
    int lane = threadIdx.x & 31;
    if (gw >= Nn * Hn) return;
    int n = gw / Hn;
    int h = gw - n * Hn;
    int beg = rowptr[n];
    int end = rowptr[n + 1];
    float a1n = a1[n * Hn + h];

    // pass 1: max logit
    float m = -1e30f;
    for (int e = beg + lane; e < end; e += 32) {
        float s = a1n + a2[srcs[e] * Hn + h];
        s = (s >= 0.f) ? s : 0.01f * s;
        m = fmaxf(m, s);
    }
    for (int o = 16; o; o >>= 1) m = fmaxf(m, __shfl_xor_sync(0xffffffffu, m, o));

    // pass 2: denom
    float den = 0.f;
    for (int e = beg + lane; e < end; e += 32) {
        float s = a1n + a2[srcs[e] * Hn + h];
        s = (s >= 0.f) ? s : 0.01f * s;
        den += __expf(s - m);
    }
    for (int o = 16; o; o >>= 1) den += __shfl_xor_sync(0xffffffffu, den, o);
    float inv = 1.f / den;

    // pass 3: weighted gather-accumulate
    float acc[NR];
#pragma unroll
    for (int r = 0; r < NR; r++) acc[r] = 0.f;
    const float* fbase = ft + h * HIDo + lane;

    for (int e0 = beg; e0 < end; e0 += 32) {
        int e = e0 + lane;
        float w = 0.f;
        int sv = 0;
        if (e < end) {
            sv = srcs[e];
            float s = a1n + a2[sv * Hn + h];
            s = (s >= 0.f) ? s : 0.01f * s;
            w = __expf(s - m) * inv;
        }
        int cnt = min(32, end - e0);
        for (int i = 0; i < cnt; i++) {
            float wi = __shfl_sync(0xffffffffu, w, i);
            int   si = __shfl_sync(0xffffffffu, sv, i);
            const float* fp = fbase + (size_t)si * ld;
#pragma unroll
            for (int r = 0; r < NR; r++) acc[r] = fmaf(wi, fp[r * 32], acc[r]);
        }
    }

    float* op = out + (size_t)n * ld + h * HIDo + lane;
#pragma unroll
    for (int r = 0; r < NR; r++) {
        float v = acc[r];
        op[r * 32] = (v > 0.f) ? v : expm1f(v);
    }
}

// ---------------------------------------------------------------------------
// Host launch
// ---------------------------------------------------------------------------
extern "C" void kernel_launch(void* const* d_in, const int* in_sizes, int n_in,
                              void* d_out, int out_size) {
    const float* features = (const float*)d_in[0];
    const int*   src      = (const int*)d_in[1];
    const int*   dst      = (const int*)d_in[2];
    const float* W0  = (const float*)d_in[3];
    const float* b0  = (const float*)d_in[4];
    const float* al0 = (const float*)d_in[5];
    const float* alb0= (const float*)d_in[6];
    const float* ar0 = (const float*)d_in[7];
    const float* arb0= (const float*)d_in[8];
    const float* W1  = (const float*)d_in[9];
    const float* b1  = (const float*)d_in[10];
    const float* al1 = (const float*)d_in[11];
    const float* alb1= (const float*)d_in[12];
    const float* ar1 = (const float*)d_in[13];
    const float* arb1= (const float*)d_in[14];
    const float* Wf  = (const float*)d_in[15];
    const float* bfv = (const float*)d_in[16];
    const float* alf = (const float*)d_in[17];
    const float* albf= (const float*)d_in[18];
    const float* arf = (const float*)d_in[19];
    const float* arbf= (const float*)d_in[20];

    float *bufA, *bufB, *a1, *a2;
    int *cnt, *rowptr, *cursor, *ssrc;
    cudaGetSymbolAddress((void**)&bufA, g_bufA);
    cudaGetSymbolAddress((void**)&bufB, g_bufB);
    cudaGetSymbolAddress((void**)&a1, g_a1);
    cudaGetSymbolAddress((void**)&a2, g_a2);
    cudaGetSymbolAddress((void**)&cnt, g_cnt);
    cudaGetSymbolAddress((void**)&rowptr, g_rowptr);
    cudaGetSymbolAddress((void**)&cursor, g_cursor);
    cudaGetSymbolAddress((void**)&ssrc, g_srcsorted);

    // --- CSR build (per launch; deterministic work) ---
    zero_int_kernel<<<(cN + 255) / 256, 256>>>(cnt, cN);
    hist_kernel<<<(cE + 255) / 256, 256>>>(dst, cnt, cE);
    scan_kernel<<<1, 1024>>>(cnt, rowptr, cursor, cN);
    scatter_kernel<<<(cE + 255) / 256, 256>>>(src, dst, cursor, ssrc, cE);

    const int gemmGridM = (cN + 127) / 128;
    const int warpBlocksH = (cN * cH * 32 + 255) / 256;   // warp per (n,h)
    const int warpBlocks1 = (cN * 32 + 255) / 256;        // warp per n

    // --- layer 0: features [N,512] -> ft0 [N,1024] ---
    gemm_bias_kernel<128, 128, 8, 8, 8><<<dim3(gemmGridM, 8), 256>>>(
        features, W0, b0, bufA, cN, cIN, cHH);
    logits_kernel<<<warpBlocksH, 256>>>(bufA, al0, alb0, ar0, arb0, a1, a2,
                                        cN, cH, cHID, cHH);
    aggregate_kernel<4><<<warpBlocksH, 256>>>(bufA, a1, a2, rowptr, ssrc, bufB,
                                              cN, cH, cHH);

    // --- layer 1: [N,1024] -> ft1 [N,1024] ---
    gemm_bias_kernel<128, 128, 8, 8, 8><<<dim3(gemmGridM, 8), 256>>>(
        bufB, W1, b1, bufA, cN, cHH, cHH);
    logits_kernel<<<warpBlocksH, 256>>>(bufA, al1, alb1, ar1, arb1, a1, a2,
                                        cN, cH, cHID, cHH);
    aggregate_kernel<4><<<warpBlocksH, 256>>>(bufA, a1, a2, rowptr, ssrc, bufB,
                                              cN, cH, cHH);

    // --- final layer: [N,1024] -> [N,64] ---
    gemm_bias_kernel<128, 64, 8, 8, 4><<<dim3(gemmGridM, 1), 256>>>(
        bufB, Wf, bfv, bufA, cN, cHH, cC);
    logits_kernel<<<warpBlocks1, 256>>>(bufA, alf, albf, arf, arbf, a1, a2,
                                        cN, 1, cC, cC);
    aggregate_kernel<2><<<warpBlocks1, 256>>>(bufA, a1, a2, rowptr, ssrc,
                                              (float*)d_out, cN, 1, cC);
}

// round 4
// speedup vs baseline: 1.7809x; 1.7809x over previous
#include <cuda_runtime.h>
#include <cuda_bf16.h>
#include <math.h>
#include <stdint.h>

// Problem constants (fixed by the dataset)
constexpr int cN   = 20000;
constexpr int cE   = 320000;
constexpr int cIN  = 512;
constexpr int cHID = 128;
constexpr int cH   = 8;
constexpr int cC   = 64;
constexpr int cHH  = cH * cHID;   // 1024

// ---------------------------------------------------------------------------
// Scratch (static __device__ globals; no allocation allowed)
// ---------------------------------------------------------------------------
__device__ __align__(128) float         g_ft[(size_t)cN * cHH];   // GEMM out fp32
__device__ __align__(128) __nv_bfloat16 g_Ahi[(size_t)cN * cHH];  // A hi split
__device__ __align__(128) __nv_bfloat16 g_Alo[(size_t)cN * cHH];  // A lo split
__device__ __align__(128) __nv_bfloat16 g_Bhi[cHH * cHH];         // W hi, [Nout][K]
__device__ __align__(128) __nv_bfloat16 g_Blo[cHH * cHH];
__device__ float g_a1[cN * cH];
__device__ float g_a2[cN * cH];
__device__ int   g_cnt[cN];
__device__ int   g_rowptr[cN + 1];
__device__ int   g_cursor[cN];
__device__ int   g_srcsorted[cE];

// ---------------------------------------------------------------------------
// PTX helpers (base sm_80+ ISA only — NO tcgen05, the harness lowers to sm_103)
// ---------------------------------------------------------------------------
__device__ __forceinline__ uint32_t smem_u32(const void* p) {
    uint32_t a;
    asm("{ .reg .u64 t; cvta.to.shared.u64 t, %1; cvt.u32.u64 %0, t; }" : "=r"(a) : "l"(p));
    return a;
}
__device__ __forceinline__ void cp16(uint32_t dst, const void* src, bool ok) {
    int sz = ok ? 16 : 0;
    asm volatile("cp.async.cg.shared.global [%0], [%1], 16, %2;"
                 :: "r"(dst), "l"(src), "r"(sz) : "memory");
}
__device__ __forceinline__ void cp_commit() {
    asm volatile("cp.async.commit_group;" ::: "memory");
}
__device__ __forceinline__ void mma_bf16(float* d, const uint32_t* a, const uint32_t* b) {
    asm volatile(
        "mma.sync.aligned.m16n8k16.row.col.f32.bf16.bf16.f32 "
        "{%0,%1,%2,%3}, {%4,%5,%6,%7}, {%8,%9}, {%0,%1,%2,%3};"
        : "+f"(d[0]), "+f"(d[1]), "+f"(d[2]), "+f"(d[3])
        : "r"(a[0]), "r"(a[1]), "r"(a[2]), "r"(a[3]), "r"(b[0]), "r"(b[1]));
}

// ---------------------------------------------------------------------------
// CSR build
// ---------------------------------------------------------------------------
__global__ void zero_int_kernel(int* p, int n) {
    int i = blockIdx.x * blockDim.x + threadIdx.x;
    if (i < n) p[i] = 0;
}
__global__ void hist_kernel(const int* __restrict__ dst, int* __restrict__ cnt, int e) {
    int i = blockIdx.x * blockDim.x + threadIdx.x;
    if (i < e) atomicAdd(&cnt[dst[i]], 1);
}
__global__ void scan_kernel(const int* __restrict__ cnt, int* __restrict__ rowptr,
                            int* __restrict__ cursor, int n) {
    __shared__ int sh[1024];
    int tid = threadIdx.x;
    const int CH = (n + 1023) / 1024;
    int st = tid * CH;
    int s = 0;
    for (int i = 0; i < CH; i++) {
        int idx = st + i;
        if (idx < n) s += cnt[idx];
    }
    sh[tid] = s;
    __syncthreads();
    for (int d = 1; d < 1024; d <<= 1) {
        int v = (tid >= d) ? sh[tid - d] : 0;
        __syncthreads();
        sh[tid] += v;
        __syncthreads();
    }
    int run = sh[tid] - s;
    for (int i = 0; i < CH; i++) {
        int idx = st + i;
        if (idx < n) {
            rowptr[idx] = run;
            cursor[idx] = run;
            run += cnt[idx];
        }
    }
    if (tid == 1023) rowptr[n] = sh[1023];
}
__global__ void scatter_kernel(const int* __restrict__ src, const int* __restrict__ dst,
                               int* __restrict__ cursor, int* __restrict__ out, int e) {
    int i = blockIdx.x * blockDim.x + threadIdx.x;
    if (i < e) {
        int d = dst[i];
        int pos = atomicAdd(&cursor[d], 1);
        out[pos] = src[i];
    }
}

// ---------------------------------------------------------------------------
// fp32 -> bf16 hi/lo split (first-layer features)
// ---------------------------------------------------------------------------
__global__ void split_kernel(const float* __restrict__ in,
                             __nv_bfloat16* __restrict__ hi,
                             __nv_bfloat16* __restrict__ lo, int n) {
    int i = blockIdx.x * blockDim.x + threadIdx.x;
    if (i < n) {
        float v = in[i];
        __nv_bfloat16 h = __float2bfloat16(v);
        hi[i] = h;
        lo[i] = __float2bfloat16(v - __bfloat162float(h));
    }
}

// Weight prep: head-blocked W [heads][K][HIDo] -> B [Nout][K] K-major, split
__global__ void wprep_kernel(const float* __restrict__ W,
                             __nv_bfloat16* __restrict__ Bhi,
                             __nv_bfloat16* __restrict__ Blo,
                             int K, int HIDo, int total) {
    int idx = blockIdx.x * blockDim.x + threadIdx.x;
    if (idx >= total) return;
    int n = idx / K;
    int k = idx - n * K;
    int h = n / HIDo;
    int j = n - h * HIDo;
    float w = W[(size_t)h * K * HIDo + (size_t)k * HIDo + j];
    __nv_bfloat16 hi = __float2bfloat16(w);
    Bhi[idx] = hi;
    Blo[idx] = __float2bfloat16(w - __bfloat162float(hi));
}

// ---------------------------------------------------------------------------
// Split-bf16 warp-MMA GEMM with fused bias.
//   C(fp32)[M,Nout] = A(fp32) @ W(fp32)^T  via  Ahi*Bhi + Alo*Bhi + Ahi*Blo
// A: [M,K] bf16 K-major.  B: [Nout,K] bf16 K-major.
// Tile: BM=128 x BN x BK=32, 8 warps (2x4), warp tile 64 x BN/4.
// SMEM rows padded to 80B (conflict-free for the m16n8k16 fragment pattern).
// ---------------------------------------------------------------------------
template<int BN>
__global__ __launch_bounds__(256)
void gemm_mma_kernel(const __nv_bfloat16* __restrict__ Ahi,
                     const __nv_bfloat16* __restrict__ Alo,
                     const __nv_bfloat16* __restrict__ Bhi,
                     const __nv_bfloat16* __restrict__ Blo,
                     const float* __restrict__ bias,
                     float* __restrict__ C,
                     int M, int K, int ldc) {
    constexpr int MT  = 4;          // m16 tiles per warp (64 rows)
    constexpr int WNC = BN / 4;     // cols per warp
    constexpr int NTL = WNC / 8;    // n8 tiles per warp
    constexpr int ASZ = 128 * 80;   // bytes, one A operand tile (padded rows)
    constexpr int BSZ = BN * 80;
    constexpr int STAGE = 2 * ASZ + 2 * BSZ;

    extern __shared__ char smem[];
    const uint32_t sbase = smem_u32(smem);

    const int tid = threadIdx.x;
    const int wid = tid >> 5;
    const int lid = tid & 31;
    const int wr = wid >> 2;        // 0..1
    const int wc = wid & 3;         // 0..3
    const int g  = lid >> 2;
    const int t  = lid & 3;

    const int row0 = blockIdx.x * 128;
    const int col0 = blockIdx.y * BN;

    float acc[MT][NTL][4];
#pragma unroll
    for (int m = 0; m < MT; m++)
#pragma unroll
        for (int n = 0; n < NTL; n++)
#pragma unroll
            for (int q = 0; q < 4; q++) acc[m][n][q] = 0.f;

    const int nch = K >> 5;

    auto ld_stage = [&](int s, int k0) {
        const uint32_t sb = sbase + s * STAGE;
        // A: 128 rows x 4 16B chunks, hi+lo
#pragma unroll
        for (int c = tid; c < 512; c += 256) {
            int r = c >> 2, q = c & 3;
            int gr = row0 + r;
            bool ok = gr < M;
            size_t goff = (size_t)(ok ? gr : row0) * K + k0 + q * 8;
            cp16(sb + r * 80 + q * 16, Ahi + goff, ok);
            cp16(sb + ASZ + r * 80 + q * 16, Alo + goff, ok);
        }
        // B: BN rows x 4 chunks, hi+lo (always in-bounds)
#pragma unroll
        for (int c = tid; c < BN * 4; c += 256) {
            int r = c >> 2, q = c & 3;
            size_t goff = (size_t)(col0 + r) * K + k0 + q * 8;
            cp16(sb + 2 * ASZ + r * 80 + q * 16, Bhi + goff, true);
            cp16(sb + 2 * ASZ + BSZ + r * 80 + q * 16, Blo + goff, true);
        }
    };

    ld_stage(0, 0);
    cp_commit();

    for (int i = 0; i < nch; i++) {
        if (i + 1 < nch) {
            ld_stage((i + 1) & 1, (i + 1) * 32);
            cp_commit();
            asm volatile("cp.async.wait_group 1;" ::: "memory");
        } else {
            asm volatile("cp.async.wait_group 0;" ::: "memory");
        }
        __syncthreads();

        const char* sA_hi = smem + (i & 1) * STAGE;
        const char* sA_lo = sA_hi + ASZ;
        const char* sB_hi = sA_lo + ASZ;
        const char* sB_lo = sB_hi + BSZ;

#pragma unroll
        for (int ks = 0; ks < 2; ks++) {
            const int kb = ks * 32 + t * 4;   // byte offset within padded row

            uint32_t bh[NTL][2], bl[NTL][2];
#pragma unroll
            for (int n = 0; n < NTL; n++) {
                int off = (wc * WNC + n * 8 + g) * 80 + kb;
                bh[n][0] = *(const uint32_t*)(sB_hi + off);
                bh[n][1] = *(const uint32_t*)(sB_hi + off + 16);
                bl[n][0] = *(const uint32_t*)(sB_lo + off);
                bl[n][1] = *(const uint32_t*)(sB_lo + off + 16);
            }
#pragma unroll
            for (int m = 0; m < MT; m++) {
                int off = (wr * 64 + m * 16 + g) * 80 + kb;
                uint32_t ah[4], al[4];
                ah[0] = *(const uint32_t*)(sA_hi + off);
                ah[1] = *(const uint32_t*)(sA_hi + off + 640);
                ah[2] = *(const uint32_t*)(sA_hi + off + 16);
                ah[3] = *(const uint32_t*)(sA_hi + off + 656);
                al[0] = *(const uint32_t*)(sA_lo + off);
                al[1] = *(const uint32_t*)(sA_lo + off + 640);
                al[2] = *(const uint32_t*)(sA_lo + off + 16);
                al[3] = *(const uint32_t*)(sA_lo + off + 656);
#pragma unroll
                for (int n = 0; n < NTL; n++) {
                    mma_bf16(acc[m][n], ah, bh[n]);
                    mma_bf16(acc[m][n], al, bh[n]);
                    mma_bf16(acc[m][n], ah, bl[n]);
                }
            }
        }
        __syncthreads();
    }

    // Epilogue: add bias, store fp32
#pragma unroll
    for (int m = 0; m < MT; m++) {
        int r0r = row0 + wr * 64 + m * 16 + g;
        int r1r = r0r + 8;
#pragma unroll
        for (int n = 0; n < NTL; n++) {
            int cc = col0 + wc * WNC + n * 8 + t * 2;
            float bx = bias[cc], by = bias[cc + 1];
            if (r0r < M) {
                float2 v = make_float2(acc[m][n][0] + bx, acc[m][n][1] + by);
                *(float2*)(C + (size_t)r0r * ldc + cc) = v;
            }
            if (r1r < M) {
                float2 v = make_float2(acc[m][n][2] + bx, acc[m][n][3] + by);
                *(float2*)(C + (size_t)r1r * ldc + cc) = v;
            }
        }
    }
}

// ---------------------------------------------------------------------------
// Per-node attention logits (one warp per (node, head))
// ---------------------------------------------------------------------------
__global__ void logits_kernel(const float* __restrict__ ft,
                              const float* __restrict__ al, const float* __restrict__ alb,
                              const float* __restrict__ ar, const float* __restrict__ arb,
                              float* __restrict__ a1, float* __restrict__ a2,
                              int Nn, int Hn, int HIDo, int ld) {
    int gw   = (blockIdx.x * blockDim.x + threadIdx.x) >> 5;
    int lane = threadIdx.x & 31;
    if (gw >= Nn * Hn) return;
    int n = gw / Hn;
    int h = gw - n * Hn;
    const float* fp = ft + (size_t)n * ld + h * HIDo;
    float s1 = 0.f, s2 = 0.f;
    for (int j = lane; j < HIDo; j += 32) {
        float f = fp[j];
        s1 = fmaf(f, al[h * HIDo + j], s1);
        s2 = fmaf(f, ar[h * HIDo + j], s2);
    }
    for (int o = 16; o; o >>= 1) {
        s1 += __shfl_xor_sync(0xffffffffu, s1, o);
        s2 += __shfl_xor_sync(0xffffffffu, s2, o);
    }
    if (lane == 0) {
        a1[n * Hn + h] = s1 + alb[h];
        a2[n * Hn + h] = s2 + arb[h];
    }
}

// ---------------------------------------------------------------------------
// Edge-softmax + aggregation + ELU.  One warp per (node, head).
// SPLIT: write bf16 hi/lo (feeds next GEMM); else fp32 out.
// ---------------------------------------------------------------------------
template<int NR, bool SPLIT>
__global__ void aggregate_kernel(const float* __restrict__ ft,
                                 const float* __restrict__ a1,
                                 const float* __restrict__ a2,
                                 const int* __restrict__ rowptr,
                                 const int* __restrict__ srcs,
                                 float* __restrict__ out,
                                 __nv_bfloat16* __restrict__ outHi,
                                 __nv_bfloat16* __restrict__ outLo,
                                 int Nn, int Hn, int ld) {
    constexpr int HIDo = NR * 32;
    int gw   = (blockIdx.x * blockDim.x + threadIdx.x) >> 5;
    int lane = threadIdx.x & 31;
    if (gw >= Nn * Hn) return;
    int n = gw / Hn;
    int h = gw - n * Hn;
    int beg = rowptr[n];
    int end = rowptr[n + 1];
    float a1n = a1[n * Hn + h];

    float m = -1e30f;
    for (int e = beg + lane; e < end; e += 32) {
        float s = a1n + a2[srcs[e] * Hn + h];
        s = (s >= 0.f) ? s : 0.01f * s;
        m = fmaxf(m, s);
    }
    for (int o = 16; o; o >>= 1) m = fmaxf(m, __shfl_xor_sync(0xffffffffu, m, o));

    float den = 0.f;
    for (int e = beg + lane; e < end; e += 32) {
        float s = a1n + a2[srcs[e] * Hn + h];
        s = (s >= 0.f) ? s : 0.01f * s;
        den += __expf(s - m);
    }
    for (int o = 16; o; o >>= 1) den += __shfl_xor_sync(0xffffffffu, den, o);
    float inv = 1.f / den;

    float acc[NR];
#pragma unroll
    for (int r = 0; r < NR; r++) acc[r] = 0.f;
    const float* fbase = ft + h * HIDo + lane;

    for (int e0 = beg; e0 < end; e0 += 32) {
        int e = e0 + lane;
        float w = 0.f;
        int sv = 0;
        if (e < end) {
            sv = srcs[e];
            float s = a1n + a2[sv * Hn + h];
            s = (s >= 0.f) ? s : 0.01f * s;
            w = __expf(s - m) * inv;
        }
        int cnt = min(32, end - e0);
        for (int i = 0; i < cnt; i++) {
            float wi = __shfl_sync(0xffffffffu, w, i);
            int   si = __shfl_sync(0xffffffffu, sv, i);
            const float* fp = fbase + (size_t)si * ld;
#pragma unroll
            for (int r = 0; r < NR; r++) acc[r] = fmaf(wi, fp[r * 32], acc[r]);
        }
    }

    size_t obase = (size_t)n * ld + h * HIDo + lane;
#pragma unroll
    for (int r = 0; r < NR; r++) {
        float v = acc[r];
        v = (v > 0.f) ? v : expm1f(v);
        if (SPLIT) {
            __nv_bfloat16 hi = __float2bfloat16(v);
            outHi[obase + r * 32] = hi;
            outLo[obase + r * 32] = __float2bfloat16(v - __bfloat162float(hi));
        } else {
            out[obase + r * 32] = v;
        }
    }
}

// ---------------------------------------------------------------------------
// Host launch
// ---------------------------------------------------------------------------
extern "C" void kernel_launch(void* const* d_in, const int* in_sizes, int n_in,
                              void* d_out, int out_size) {
    const float* features = (const float*)d_in[0];
    const int*   src      = (const int*)d_in[1];
    const int*   dst      = (const int*)d_in[2];
    const float* W0  = (const float*)d_in[3];
    const float* b0  = (const float*)d_in[4];
    const float* al0 = (const float*)d_in[5];
    const float* alb0= (const float*)d_in[6];
    const float* ar0 = (const float*)d_in[7];
    const float* arb0= (const float*)d_in[8];
    const float* W1  = (const float*)d_in[9];
    const float* b1  = (const float*)d_in[10];
    const float* al1 = (const float*)d_in[11];
    const float* alb1= (const float*)d_in[12];
    const float* ar1 = (const float*)d_in[13];
    const float* arb1= (const float*)d_in[14];
    const float* Wf  = (const float*)d_in[15];
    const float* bfv = (const float*)d_in[16];
    const float* alf = (const float*)d_in[17];
    const float* albf= (const float*)d_in[18];
    const float* arf = (const float*)d_in[19];
    const float* arbf= (const float*)d_in[20];

    float *ft, *a1, *a2;
    __nv_bfloat16 *Ahi, *Alo, *Bhi, *Blo;
    int *cnt, *rowptr, *cursor, *ssrc;
    cudaGetSymbolAddress((void**)&ft,  g_ft);
    cudaGetSymbolAddress((void**)&Ahi, g_Ahi);
    cudaGetSymbolAddress((void**)&Alo, g_Alo);
    cudaGetSymbolAddress((void**)&Bhi, g_Bhi);
    cudaGetSymbolAddress((void**)&Blo, g_Blo);
    cudaGetSymbolAddress((void**)&a1, g_a1);
    cudaGetSymbolAddress((void**)&a2, g_a2);
    cudaGetSymbolAddress((void**)&cnt, g_cnt);
    cudaGetSymbolAddress((void**)&rowptr, g_rowptr);
    cudaGetSymbolAddress((void**)&cursor, g_cursor);
    cudaGetSymbolAddress((void**)&ssrc, g_srcsorted);

    // SMEM: 2 stages * (2*A(128*80) + 2*B(BN*80))
    constexpr int SMEM128 = 2 * (2 * 128 * 80 + 2 * 128 * 80);  // 81920
    constexpr int SMEM64  = 2 * (2 * 128 * 80 + 2 * 64 * 80);   // 61440
    cudaFuncSetAttribute(gemm_mma_kernel<128>,
                         cudaFuncAttributeMaxDynamicSharedMemorySize, SMEM128);
    cudaFuncSetAttribute(gemm_mma_kernel<64>,
                         cudaFuncAttributeMaxDynamicSharedMemorySize, SMEM64);

    // --- CSR build ---
    zero_int_kernel<<<(cN + 255) / 256, 256>>>(cnt, cN);
    hist_kernel<<<(cE + 255) / 256, 256>>>(dst, cnt, cE);
    scan_kernel<<<1, 1024>>>(cnt, rowptr, cursor, cN);
    scatter_kernel<<<(cE + 255) / 256, 256>>>(src, dst, cursor, ssrc, cE);

    const int gridM = (cN + 127) / 128;   // 157
    const int warpBlocksH = (cN * cH * 32 + 255) / 256;
    const int warpBlocks1 = (cN * 32 + 255) / 256;

    // --- layer 0 ---
    split_kernel<<<(cN * cIN + 255) / 256, 256>>>(features, Ahi, Alo, cN * cIN);
    wprep_kernel<<<(cHH * cIN + 255) / 256, 256>>>(W0, Bhi, Blo, cIN, cHID, cHH * cIN);
    gemm_mma_kernel<128><<<dim3(gridM, 8), 256, SMEM128>>>(Ahi, Alo, Bhi, Blo, b0, ft,
                                                           cN, cIN, cHH);
    logits_kernel<<<warpBlocksH, 256>>>(ft, al0, alb0, ar0, arb0, a1, a2, cN, cH, cHID, cHH);
    aggregate_kernel<4, true><<<warpBlocksH, 256>>>(ft, a1, a2, rowptr, ssrc,
                                                    nullptr, Ahi, Alo, cN, cH, cHH);

    // --- layer 1 ---
    wprep_kernel<<<(cHH * cHH + 255) / 256, 256>>>(W1, Bhi, Blo, cHH, cHID, cHH * cHH);
    gemm_mma_kernel<128><<<dim3(gridM, 8), 256, SMEM128>>>(Ahi, Alo, Bhi, Blo, b1, ft,
                                                           cN, cHH, cHH);
    logits_kernel<<<warpBlocksH, 256>>>(ft, al1, alb1, ar1, arb1, a1, a2, cN, cH, cHID, cHH);
    aggregate_kernel<4, true><<<warpBlocksH, 256>>>(ft, a1, a2, rowptr, ssrc,
                                                    nullptr, Ahi, Alo, cN, cH, cHH);

    // --- final layer ---
    wprep_kernel<<<(cC * cHH + 255) / 256, 256>>>(Wf, Bhi, Blo, cHH, cC, cC * cHH);
    gemm_mma_kernel<64><<<dim3(gridM, 1), 256, SMEM64>>>(Ahi, Alo, Bhi, Blo, bfv, ft,
                                                         cN, cHH, cC);
    logits_kernel<<<warpBlocks1, 256>>>(ft, alf, albf, arf, arbf, a1, a2, cN, 1, cC, cC);
    aggregate_kernel<2, false><<<warpBlocks1, 256>>>(ft, a1, a2, rowptr, ssrc,
                                                     (float*)d_out, nullptr, nullptr,
                                                     cN, 1, cC);
}